// round 9
// baseline (speedup 1.0000x reference)
#include <cuda_runtime.h>
#include <math.h>

// Problem constants (fixed by reference)
#define VOCAB 100000
#define DIM   128
#define BATCH 16384
#define CTX   10
#define NEG   5

#define WARPS_PER_BLOCK 8
#define THREADS (WARPS_PER_BLOCK * 32)
#define ELEMS_PER_WARP 2
#define NUM_BLOCKS (BATCH / (WARPS_PER_BLOCK * ELEMS_PER_WARP))   // 1024: single CTA wave

// Scratch (no cudaMalloc allowed)
__device__ double       g_accum  = 0.0;
__device__ unsigned int g_ticket = 0;

__device__ __forceinline__ float log_sigmoid(float x) {
    return fminf(x, 0.0f) - log1pf(expf(-fabsf(x)));
}

// 256-bit row-slice loads: 16 lanes x 32B = one 512B embedding row.
// u-table: inline evict_last (legal on .v8.b32 per sm_103 ptxas).
__device__ __forceinline__ void ldg256_keep(const float* p, float* v) {
    unsigned r0,r1,r2,r3,r4,r5,r6,r7;
    asm("ld.global.nc.L2::evict_last.v8.b32 {%0,%1,%2,%3,%4,%5,%6,%7}, [%8];"
        : "=r"(r0),"=r"(r1),"=r"(r2),"=r"(r3),
          "=r"(r4),"=r"(r5),"=r"(r6),"=r"(r7)
        : "l"(p));
    v[0]=__uint_as_float(r0); v[1]=__uint_as_float(r1);
    v[2]=__uint_as_float(r2); v[3]=__uint_as_float(r3);
    v[4]=__uint_as_float(r4); v[5]=__uint_as_float(r5);
    v[6]=__uint_as_float(r6); v[7]=__uint_as_float(r7);
}
__device__ __forceinline__ void ldg256(const float* p, float* v) {
    unsigned r0,r1,r2,r3,r4,r5,r6,r7;
    asm("ld.global.nc.v8.b32 {%0,%1,%2,%3,%4,%5,%6,%7}, [%8];"
        : "=r"(r0),"=r"(r1),"=r"(r2),"=r"(r3),
          "=r"(r4),"=r"(r5),"=r"(r6),"=r"(r7)
        : "l"(p));
    v[0]=__uint_as_float(r0); v[1]=__uint_as_float(r1);
    v[2]=__uint_as_float(r2); v[3]=__uint_as_float(r3);
    v[4]=__uint_as_float(r4); v[5]=__uint_as_float(r5);
    v[6]=__uint_as_float(r6); v[7]=__uint_as_float(r7);
}

__device__ __forceinline__ float dot8(const float* a, const float* b) {
    float d = a[0]*b[0];
    d += a[1]*b[1]; d += a[2]*b[2]; d += a[3]*b[3];
    d += a[4]*b[4]; d += a[5]*b[5]; d += a[6]*b[6]; d += a[7]*b[7];
    return d;
}

__global__ __launch_bounds__(THREADS)
void cbow_loss_fused(const int* __restrict__ pos_u,   // [B, CTX]
                     const int* __restrict__ pos_w,   // [B]
                     const int* __restrict__ neg_w,   // [B, NEG]
                     const float* __restrict__ u_w,   // [VOCAB, 128]
                     const float* __restrict__ w_w,   // [VOCAB, 128]
                     float* __restrict__ out)
{
    const int warp = threadIdx.x >> 5;
    const int lane = threadIdx.x & 31;
    const int half = lane >> 4;        // 0: lanes 0-15, 1: lanes 16-31
    const int sl   = lane & 15;        // slice within row (8 floats each)
    const int b0 = (blockIdx.x * WARPS_PER_BLOCK + warp) * ELEMS_PER_WARP;

    float ls = 0.0f;   // lane0 accumulates logsigmoid terms

    #pragma unroll
    for (int e = 0; e < ELEMS_PER_WARP; ++e) {
        const int b = b0 + e;
        const int* pu = pos_u + b * CTX;
        const int* nw = neg_w + b * NEG;

        // --- context gather-sum: 5 LDG.256, each fetching TWO rows (one per half-warp) ---
        float usum[8] = {0.f,0.f,0.f,0.f,0.f,0.f,0.f,0.f};
        #pragma unroll
        for (int c = 0; c < CTX; c += 2) {
            int ia = __ldg(pu + c);
            int ib = __ldg(pu + c + 1);
            int row = half ? ib : ia;
            float v[8];
            ldg256_keep(u_w + (size_t)row * DIM + sl * 8, v);
            #pragma unroll
            for (int i = 0; i < 8; ++i) usum[i] += v[i];
        }
        // merge the two half-warp partial sums: every lane gets the total for its slice
        #pragma unroll
        for (int i = 0; i < 8; ++i)
            usum[i] += __shfl_xor_sync(0xFFFFFFFFu, usum[i], 16);

        // --- w-phase: 3 LDG.256 cover pos + 5 neg rows ---
        float pd = 0.f, nd = 0.f;
        {   // pair (pos, neg0)
            int ia = __ldg(pos_w + b);
            int ib = __ldg(nw + 0);
            int row = half ? ib : ia;
            float v[8];
            ldg256(w_w + (size_t)row * DIM + sl * 8, v);
            float d = dot8(usum, v);
            if (half == 0) pd = d; else nd = d;
        }
        #pragma unroll
        for (int t = 0; t < 2; ++t) {   // pairs (neg1,neg2), (neg3,neg4)
            int ia = __ldg(nw + 1 + 2 * t);
            int ib = __ldg(nw + 2 + 2 * t);
            int row = half ? ib : ia;
            float v[8];
            ldg256(w_w + (size_t)row * DIM + sl * 8, v);
            nd += dot8(usum, v);
        }

        // --- 32-lane butterfly reduces both dots (halves sum automatically) ---
        #pragma unroll
        for (int off = 16; off > 0; off >>= 1) {
            pd += __shfl_xor_sync(0xFFFFFFFFu, pd, off);
            nd += __shfl_xor_sync(0xFFFFFFFFu, nd, off);
        }
        if (lane == 0)
            ls += log_sigmoid(pd) + log_sigmoid(-nd);
    }

    __shared__ float s_part[WARPS_PER_BLOCK];
    if (lane == 0)
        s_part[warp] = ls;
    __syncthreads();

    // --- featherweight epilogue: one double atomic per block + ticket ---
    if (threadIdx.x == 0) {
        float acc = 0.f;
        #pragma unroll
        for (int i = 0; i < WARPS_PER_BLOCK; ++i) acc += s_part[i];
        atomicAdd(&g_accum, (double)acc);   // order-insensitive in double
        __threadfence();
        unsigned int t = atomicAdd(&g_ticket, 1u);
        if (t == NUM_BLOCKS - 1) {
            __threadfence();
            double total = g_accum;
            out[0] = (float)(-total);       // loss = -(sum of logsigmoids)
            g_accum  = 0.0;
            g_ticket = 0;
        }
    }
}

extern "C" void kernel_launch(void* const* d_in, const int* in_sizes, int n_in,
                              void* d_out, int out_size) {
    const int*   pos_u = (const int*)d_in[0];
    const int*   pos_w = (const int*)d_in[1];
    const int*   neg_w = (const int*)d_in[2];
    const float* u_w   = (const float*)d_in[3];
    const float* w_w   = (const float*)d_in[4];
    float* out = (float*)d_out;

    cbow_loss_fused<<<NUM_BLOCKS, THREADS>>>(pos_u, pos_w, neg_w, u_w, w_w, out);
}